// round 1
// baseline (speedup 1.0000x reference)
#include <cuda_runtime.h>

// MaxOccurrencePool: sliding-window (K=9) mode-with-tie-average + max-count over
// integer values 0..4, values 1..4 counted, bin0 only when window empty.
// x: [B=8, L=131072, C=16] f32. Outputs: out [B, L-1, C] f32 then density [B, L-1, C] f32.

#define BB    8
#define LL    131072
#define CC    16
#define LOUT  131071          // L - 1 output positions along L
#define CHUNK 36              // multiple of 9 (ring period)
#define NCH   3641            // ceil(LOUT / CHUNK)
#define NTHREADS_TOTAL (NCH * 32)
#define NBLK  ((NTHREADS_TOTAL + 127) / 128)

// one-hot byte delta for value iv in 0..4: byte (iv-1) set to 1, or 0 for iv==0.
// Single clamped funnel shift: high32 of (0:0x01000000) << (8*iv), shift clamped at 32.
__device__ __forceinline__ unsigned dlt(float f) {
    int iv = (int)f;
    return __funnelshift_lc(0x01000000u, 0u, iv << 3);
}

// h = packed byte counts (c1..c4). Produce out (tie-averaged argmax) + density.
__device__ __forceinline__ void consume(unsigned h, float &outv, float &den) {
    unsigned c1 = h & 0xFFu;
    unsigned c2 = (h >> 8) & 0xFFu;
    unsigned c3 = (h >> 16) & 0xFFu;
    unsigned c4 = h >> 24;
    unsigned m  = max(max(c1, c2), max(c3, c4));
    // tied bytes become 0x0F + 1 -> carry into bit4 of each byte
    unsigned y   = (h + 0x10101010u) - m * 0x01010101u;
    unsigned msk = y & 0x10101010u;                 // 0x10 per tied byte
    unsigned s16 = __dp4a(msk, 0x04030201u, 0u);    // 16 * sum(tied indices)
    unsigned n16 = __dp4a(msk, 0x01010101u, 0u);    // 16 * num ties
    float o = __fdividef((float)s16, (float)n16);   // == s/n
    outv = (m == 0u) ? 0.0f : o;                    // empty window -> bin0 -> 0
    den  = (float)max(m, 1u);                       // empty window -> density 1
}

template <bool FULL>
__device__ __forceinline__ void run_chunk(const float4 *__restrict__ xin,
                                          float4 *__restrict__ outp,
                                          float4 *__restrict__ denp,
                                          int l0) {
    unsigned h0 = 0, h1 = 0, h2 = 0, h3 = 0;
    unsigned ring[9][4];

    // Prefill hist with positions p = l0-4 .. l0+4 (9 slots). OOB (padding) -> 0.
    #pragma unroll
    for (int k = 0; k < 9; k++) {
        int p = l0 - 4 + k;
        float4 v = make_float4(0.f, 0.f, 0.f, 0.f);
        if ((unsigned)p < (unsigned)LL) v = xin[p * 4];
        unsigned d0 = dlt(v.x), d1 = dlt(v.y), d2 = dlt(v.z), d3 = dlt(v.w);
        h0 += d0; h1 += d1; h2 += d2; h3 += d3;
        ring[k][0] = d0; ring[k][1] = d1; ring[k][2] = d2; ring[k][3] = d3;
    }

    // Software-pipelined main loop; slot (l0-4+j) mod 9 == (l0+5+j) mod 9 == ji.
    float4 cur = make_float4(0.f, 0.f, 0.f, 0.f);
    {
        int p = l0 + 5;
        if (FULL || (unsigned)p < (unsigned)LL) cur = xin[p * 4];
    }
    #pragma unroll 1
    for (int jo = 0; jo < CHUNK / 9; jo++) {
        #pragma unroll
        for (int ji = 0; ji < 9; ji++) {
            int j = jo * 9 + ji;
            int l = l0 + j;
            unsigned d0 = dlt(cur.x), d1 = dlt(cur.y), d2 = dlt(cur.z), d3 = dlt(cur.w);

            // prefetch next element early
            float4 nxt = make_float4(0.f, 0.f, 0.f, 0.f);
            int pn = l0 + 6 + j;
            if (FULL) {
                nxt = xin[pn * 4];
            } else if ((unsigned)pn < (unsigned)LL) {
                nxt = xin[pn * 4];
            }

            h0 += d0 - ring[ji][0]; ring[ji][0] = d0;
            h1 += d1 - ring[ji][1]; ring[ji][1] = d1;
            h2 += d2 - ring[ji][2]; ring[ji][2] = d2;
            h3 += d3 - ring[ji][3]; ring[ji][3] = d3;

            float4 o, dn;
            consume(h0, o.x, dn.x);
            consume(h1, o.y, dn.y);
            consume(h2, o.z, dn.z);
            consume(h3, o.w, dn.w);

            if (FULL || l < LOUT) {
                outp[l * 4] = o;
                denp[l * 4] = dn;
            }
            cur = nxt;
        }
    }
}

__global__ void __launch_bounds__(128)
MaxOccurrencePool_kernel(const float *__restrict__ x, float *__restrict__ out) {
    int t = blockIdx.x * 128 + threadIdx.x;
    int chunk = t >> 5;
    if (chunk >= NCH) return;
    int lane = t & 31;
    int cg = lane & 3;        // channel group (4 floats)
    int b  = lane >> 2;       // batch
    int l0 = chunk * CHUNK;

    const float4 *xin = reinterpret_cast<const float4 *>(x) + (size_t)b * LL * 4 + cg;
    float4 *outp = reinterpret_cast<float4 *>(out) + (size_t)b * LOUT * 4 + cg;
    float4 *denp = outp + (size_t)BB * LOUT * 4;   // density tensor follows out

    if (l0 + CHUNK + 5 < LL)
        run_chunk<true>(xin, outp, denp, l0);
    else
        run_chunk<false>(xin, outp, denp, l0);
}

extern "C" void kernel_launch(void* const* d_in, const int* in_sizes, int n_in,
                              void* d_out, int out_size) {
    const float *x = (const float *)d_in[0];
    float *out = (float *)d_out;
    MaxOccurrencePool_kernel<<<NBLK, 128>>>(x, out);
}

// round 2
// speedup vs baseline: 1.0679x; 1.0679x over previous
#include <cuda_runtime.h>

// MaxOccurrencePool: sliding-window (K=9) mode-with-tie-average + max-count over
// integer values 0..4 (values 1..4 counted, bin0 only when window empty).
// x: [B=8, L=131072, C=16] f32. Outputs: out [B, L-1, C] f32, then density [B, L-1, C] f32.
//
// R2: CHUNK 36->18 (more warps; halo re-reads are L2 hits since input < L2),
//     ring stores nibble-packed raw values (9 regs vs 36) to lift reg-limited
//     occupancy, streaming stores to protect input L2 residency.

#define BB    8
#define LL    131072
#define CC    16
#define LOUT  131071          // L - 1 output positions along L
#define CHUNK 18              // multiple of 9 (ring period)
#define NCH   7282            // ceil(LOUT / CHUNK)
#define NBLK  ((NCH * 32 + 127) / 128)

// one-hot byte delta for value iv in 0..4: byte (iv-1) = 1, or 0 for iv==0.
// high-32 of (0x01000000 : 0) << (8*iv), shift clamped at 32.
__device__ __forceinline__ unsigned dsh(unsigned iv) {
    return __funnelshift_lc(0x01000000u, 0u, iv << 3);
}

// h = packed byte counts (c1..c4). Produce out (tie-averaged argmax) + density.
__device__ __forceinline__ void consume(unsigned h, float &outv, float &den) {
    unsigned c1 = h & 0xFFu;
    unsigned c2 = (h >> 8) & 0xFFu;
    unsigned c3 = (h >> 16) & 0xFFu;
    unsigned c4 = h >> 24;
    unsigned m  = max(max(c1, c2), max(c3, c4));
    // tied bytes (== m, m <= 9) carry into bit4 of their byte
    unsigned y   = (h + 0x10101010u) - m * 0x01010101u;
    unsigned msk = y & 0x10101010u;                 // 0x10 per tied byte
    unsigned s16 = __dp4a(msk, 0x04030201u, 0u);    // 16 * sum(tied indices)
    unsigned n16 = __dp4a(msk, 0x01010101u, 0u);    // 16 * num ties
    float o = __fdividef((float)s16, (float)n16);   // == s/n
    outv = (m == 0u) ? 0.0f : o;                    // empty window -> bin0 -> 0
    den  = (float)max(m, 1u);                       // empty window -> density 1
}

template <bool FULL>
__device__ __forceinline__ void run_chunk(const float4 *__restrict__ xin,
                                          float4 *__restrict__ outp,
                                          float4 *__restrict__ denp,
                                          int l0) {
    unsigned h0 = 0, h1 = 0, h2 = 0, h3 = 0;
    unsigned ring[9];                 // nibble-packed raw values of 4 channels

    // Prefill with positions p = l0-4 .. l0+4. OOB (padding) -> value 0.
    #pragma unroll
    for (int k = 0; k < 9; k++) {
        int p = l0 - 4 + k;
        float4 v = make_float4(0.f, 0.f, 0.f, 0.f);
        if ((unsigned)p < (unsigned)LL) v = xin[p * 4];
        unsigned i0 = (unsigned)(int)v.x, i1 = (unsigned)(int)v.y;
        unsigned i2 = (unsigned)(int)v.z, i3 = (unsigned)(int)v.w;
        ring[k] = i0 | (i1 << 4) | (i2 << 8) | (i3 << 12);
        h0 += dsh(i0); h1 += dsh(i1); h2 += dsh(i2); h3 += dsh(i3);
    }

    // slot (l0-4+j) mod 9 == (l0+5+j) mod 9 == ji  (CHUNK multiple of 9)
    float4 cur = make_float4(0.f, 0.f, 0.f, 0.f);
    {
        int p = l0 + 5;
        if (FULL || (unsigned)p < (unsigned)LL) cur = xin[p * 4];
    }
    #pragma unroll 1
    for (int jo = 0; jo < CHUNK / 9; jo++) {
        #pragma unroll
        for (int ji = 0; ji < 9; ji++) {
            int l = l0 + jo * 9 + ji;
            unsigned i0 = (unsigned)(int)cur.x, i1 = (unsigned)(int)cur.y;
            unsigned i2 = (unsigned)(int)cur.z, i3 = (unsigned)(int)cur.w;

            // prefetch next element early
            float4 nxt = make_float4(0.f, 0.f, 0.f, 0.f);
            int pn = l + 6;
            if (FULL) {
                nxt = xin[pn * 4];
            } else if ((unsigned)pn < (unsigned)LL) {
                nxt = xin[pn * 4];
            }

            unsigned old = ring[ji];
            ring[ji] = i0 | (i1 << 4) | (i2 << 8) | (i3 << 12);

            // outgoing one-hot recomputed from packed nibbles: amt = nib*8
            unsigned od0 = __funnelshift_lc(0x01000000u, 0u, (old << 3) & 0x78u);
            unsigned od1 = __funnelshift_lc(0x01000000u, 0u, (old >> 1) & 0x78u);
            unsigned od2 = __funnelshift_lc(0x01000000u, 0u, (old >> 5) & 0x78u);
            unsigned od3 = __funnelshift_lc(0x01000000u, 0u, (old >> 9) & 0x78u);

            h0 += dsh(i0) - od0;
            h1 += dsh(i1) - od1;
            h2 += dsh(i2) - od2;
            h3 += dsh(i3) - od3;

            float4 o, dn;
            consume(h0, o.x, dn.x);
            consume(h1, o.y, dn.y);
            consume(h2, o.z, dn.z);
            consume(h3, o.w, dn.w);

            if (FULL || l < LOUT) {
                __stcs(&outp[l * 4], o);
                __stcs(&denp[l * 4], dn);
            }
            cur = nxt;
        }
    }
}

__global__ void __launch_bounds__(128, 8)
MaxOccurrencePool_kernel(const float *__restrict__ x, float *__restrict__ out) {
    int t = blockIdx.x * 128 + threadIdx.x;
    int chunk = t >> 5;
    if (chunk >= NCH) return;
    int lane = t & 31;
    int cg = lane & 3;        // channel group (4 floats)
    int b  = lane >> 2;       // batch
    int l0 = chunk * CHUNK;

    const float4 *xin = reinterpret_cast<const float4 *>(x) + (size_t)b * LL * 4 + cg;
    float4 *outp = reinterpret_cast<float4 *>(out) + (size_t)b * LOUT * 4 + cg;
    float4 *denp = outp + (size_t)BB * LOUT * 4;   // density tensor follows out

    if (l0 + CHUNK + 5 < LL)
        run_chunk<true>(xin, outp, denp, l0);
    else
        run_chunk<false>(xin, outp, denp, l0);
}

extern "C" void kernel_launch(void* const* d_in, const int* in_sizes, int n_in,
                              void* d_out, int out_size) {
    const float *x = (const float *)d_in[0];
    float *out = (float *)d_out;
    MaxOccurrencePool_kernel<<<NBLK, 128>>>(x, out);
}